// round 14
// baseline (speedup 1.0000x reference)
#include <cuda_runtime.h>

#define NQ   2048
#define NS   320
#define DIM  256
#define NWAY 20

typedef unsigned long long u64;

__device__ float g_sproj[NS * DIM];

// ---- packed f32x2 helpers ----
__device__ __forceinline__ u64 add2(u64 a, u64 b) {
    u64 d; asm("add.rn.f32x2 %0, %1, %2;" : "=l"(d) : "l"(a), "l"(b)); return d;
}
__device__ __forceinline__ u64 fma2(u64 a, u64 b, u64 c) {
    u64 d; asm("fma.rn.f32x2 %0, %1, %2, %3;" : "=l"(d) : "l"(a), "l"(b), "l"(c)); return d;
}
__device__ __forceinline__ u64 dup2(float x) {
    u64 r; unsigned xi = __float_as_uint(x);
    asm("mov.b64 %0, {%1, %1};" : "=l"(r) : "r"(xi)); return r;
}
__device__ __forceinline__ float lo2(u64 v) { return __uint_as_float((unsigned)v); }
__device__ __forceinline__ float hi2(u64 v) { return __uint_as_float((unsigned)(v >> 32)); }

__device__ __forceinline__ void cpa16(void* dst, const void* src) {
    unsigned sa = (unsigned)__cvta_generic_to_shared(dst);
    asm volatile("cp.async.cg.shared.global [%0], [%1], 16;" :: "r"(sa), "l"(src));
}

// ---------------------------------------------------------------------------
// Kernel 1: sproj only. 16m x 64n tiles, BK=64, double-buffered, grid 4x20.
//   per thread: 1m x 4n; per k: 1 LDS.64 (A dup) + 1 LDS.128 (B) + 2 fma2
// ---------------------------------------------------------------------------
#define SBK    64
#define SPADA  17            // u64 stride per k-row of AsD (16 m + 1)
#define SPADB  68            // float stride per k-row of Bs
#define SASTG  (SBK * SPADA) // 1088 u64
#define SBSTG  (SBK * SPADB) // 4352 float

__global__ void __launch_bounds__(256) sproj_kernel(
    const float* __restrict__ support, const float* __restrict__ W1,
    const float* __restrict__ b1)
{
    extern __shared__ __align__(16) unsigned char psm[];
    u64*   AsD = (u64*)psm;                   // 2 * SASTG
    float* Bs  = (float*)(AsD + 2 * SASTG);   // 2 * SBSTG

    const int n0 = blockIdx.x * 64;
    const int m0 = blockIdx.y * 16;
    const float* Bmat = W1 + DIM * DIM;       // W1[256:512]

    const int tid = threadIdx.x;
    const int tx = tid & 15;                  // 4n
    const int ty = tid >> 4;                  // m (0..15)

    // A loader: m = tid>>4 (0..15), k float4 = (tid&15)*4
    const int t_m  = tid >> 4;
    const int t_k4 = (tid & 15) * 4;

    // B loader: k-row = tid>>2 (0..63), 4 float4 chunks (tid&3)+u*4
    const int b_row = tid >> 2;
    const int b_q   = tid & 3;

    const float* Arow = support + (m0 + t_m) * DIM;
    const float* Brow = Bmat + b_row * DIM + n0;

    u64 acc0 = 0ull, acc1 = 0ull;
    float4 areg;

    // prologue (stage 0)
    areg = *(const float4*)(Arow + t_k4);
    AsD[(t_k4 + 0) * SPADA + t_m] = dup2(areg.x);
    AsD[(t_k4 + 1) * SPADA + t_m] = dup2(areg.y);
    AsD[(t_k4 + 2) * SPADA + t_m] = dup2(areg.z);
    AsD[(t_k4 + 3) * SPADA + t_m] = dup2(areg.w);
    #pragma unroll
    for (int u = 0; u < 4; u++) {
        const int c4 = b_q + u * 4;
        cpa16(&Bs[b_row * SPADB + c4 * 4], Brow + c4 * 4);
    }
    asm volatile("cp.async.commit_group;");

    #pragma unroll
    for (int s = 0; s < 4; s++) {
        const int buf = s & 1;
        asm volatile("cp.async.wait_group 0;");
        __syncthreads();

        if (s < 3) {
            const int k0n = (s + 1) * SBK;
            areg = *(const float4*)(Arow + k0n + t_k4);
            #pragma unroll
            for (int u = 0; u < 4; u++) {
                const int c4 = b_q + u * 4;
                cpa16(&Bs[(buf ^ 1) * SBSTG + b_row * SPADB + c4 * 4],
                      Brow + k0n * DIM + c4 * 4);
            }
            asm volatile("cp.async.commit_group;");
        }

        const u64*   aB = AsD + buf * SASTG + ty;
        const float* bB = Bs + buf * SBSTG + tx * 4;

        #pragma unroll 16
        for (int k = 0; k < SBK; k++) {
            ulonglong2 b = *(const ulonglong2*)(bB + k * SPADB);
            u64 a = aB[k * SPADA];
            acc0 = fma2(a, b.x, acc0);
            acc1 = fma2(a, b.y, acc1);
        }

        if (s < 3) {
            u64* dst = AsD + (buf ^ 1) * SASTG;
            dst[(t_k4 + 0) * SPADA + t_m] = dup2(areg.x);
            dst[(t_k4 + 1) * SPADA + t_m] = dup2(areg.y);
            dst[(t_k4 + 2) * SPADA + t_m] = dup2(areg.z);
            dst[(t_k4 + 3) * SPADA + t_m] = dup2(areg.w);
        }
    }

    const int m = m0 + ty;
    const int n = n0 + tx * 4;
    float v[4] = { lo2(acc0), hi2(acc0), lo2(acc1), hi2(acc1) };
    #pragma unroll
    for (int j = 0; j < 4; j++)
        g_sproj[m * DIM + n + j] = v[j] + __ldg(b1 + n + j);
}

// ---------------------------------------------------------------------------
// Kernel 2: FUSED qproj + score.
//  Phase 1: qp[16,256] = query_tile @ W1[:256], computed in-smem
//           (A dup2 in smem, W1a streamed 16 k-rows at a time, double-buffered)
//  Phase 2: R11 score verbatim (|x| identity + fused Ts, atomic-free reduce)
// ---------------------------------------------------------------------------
#define QB 16
#define TPB 512
#define SPAD 260
#define CHUNKF 8320
#define ABSMASK 0x7FFFFFFF7FFFFFFFull
#define AQPAD 17            // u64 stride per k-row of Aq (16 m + 1)
#define BK2 16
#define B2PAD 260           // float stride per k-row of Bs2
#define B2STG (BK2 * B2PAD) // 4160 floats

__device__ __forceinline__ void prefetch_chunk(float* buf, int c, int tid) {
    #pragma unroll
    for (int i = 0; i < 4; i++) {
        int f   = tid + i * TPB;
        int row = f >> 6;
        int c4  = f & 63;
        cpa16(buf + row * SPAD + c4 * 4, g_sproj + (c * 32 + row) * DIM + c4 * 4);
    }
    asm volatile("cp.async.commit_group;");
}

__global__ void __launch_bounds__(TPB, 1) fused_kernel(
    const float* __restrict__ query, const float* __restrict__ W1,
    const int* __restrict__ labels, const float* __restrict__ W2,
    float* __restrict__ out)
{
    extern __shared__ __align__(16) unsigned char fsm[];
    u64*   Aq    = (u64*)fsm;                     // 256*17 u64 = 34816 B
    float* Bs2   = (float*)(Aq + DIM * AQPAD);    // 2*4160 floats
    float* sp    = Bs2 + 2 * B2STG;               // 2*8320
    float* qp    = sp + 2 * CHUNKF;               // 4096
    float* pbuf  = qp + QB * DIM;                 // 8192
    float* tbuf  = pbuf + 16 * QB * 32;           // 512
    float* part  = tbuf + 16 * 32;                // 5120
    float* tpart = part + QB * NS;                // 320
    float* sacc  = tpart + NS;                    // 320
    int*   lbl   = (int*)(sacc + QB * NWAY);      // 320

    const int tid  = threadIdx.x;
    const int warp = tid >> 5;
    const int lane = tid & 31;
    const int qbase = blockIdx.x * QB;

    // early prefetch of score chunk 0 (sproj ready via kernel order)
    prefetch_chunk(sp, 0, tid);

    // ---- phase 0: load query tile into Aq (dup2, [k][m]) + misc ----
    {
        #pragma unroll
        for (int i = 0; i < 2; i++) {
            int f  = tid + i * TPB;           // 0..1023
            int m  = f >> 6;                  // 0..15
            int kq = f & 63;                  // float4 index in row
            float4 v = *(const float4*)(query + (qbase + m) * DIM + kq * 4);
            Aq[(kq * 4 + 0) * AQPAD + m] = dup2(v.x);
            Aq[(kq * 4 + 1) * AQPAD + m] = dup2(v.y);
            Aq[(kq * 4 + 2) * AQPAD + m] = dup2(v.z);
            Aq[(kq * 4 + 3) * AQPAD + m] = dup2(v.w);
        }
        if (tid < NS) lbl[tid] = labels[tid];
        if (tid < QB * NWAY) sacc[tid] = 0.f;
    }

    // stage 0 of W1a
    {
        #pragma unroll
        for (int i = 0; i < 2; i++) {
            int f  = tid + i * TPB;
            int kr = f >> 6;                  // 0..15
            int nq = f & 63;
            cpa16(&Bs2[kr * B2PAD + nq * 4], W1 + kr * DIM + nq * 4);
        }
        asm volatile("cp.async.commit_group;");
    }

    // ---- phase 1: qproj GEMM. warp w owns n in [16w, 16w+16) ----
    {
        const int ty = lane >> 2;             // 0..7 -> m pair 2ty
        const int tx = lane & 3;              // 0..3 -> n quad
        u64 a00 = 0ull, a01 = 0ull, a10 = 0ull, a11 = 0ull;

        #pragma unroll
        for (int s2 = 0; s2 < 16; s2++) {
            const int buf = s2 & 1;
            asm volatile("cp.async.wait_group 0;");
            __syncthreads();

            if (s2 < 15) {
                const int k0n = (s2 + 1) * BK2;
                #pragma unroll
                for (int i = 0; i < 2; i++) {
                    int f  = tid + i * TPB;
                    int kr = f >> 6;
                    int nq = f & 63;
                    cpa16(&Bs2[(buf ^ 1) * B2STG + kr * B2PAD + nq * 4],
                          W1 + (k0n + kr) * DIM + nq * 4);
                }
                asm volatile("cp.async.commit_group;");
            }

            const int k0 = s2 * BK2;
            const u64*   aB = Aq + k0 * AQPAD + ty * 2;
            const float* bB = Bs2 + buf * B2STG + warp * 16 + tx * 4;

            #pragma unroll
            for (int k = 0; k < BK2; k++) {
                ulonglong2 b = *(const ulonglong2*)(bB + k * B2PAD);
                u64 a0 = aB[k * AQPAD + 0];
                u64 a1 = aB[k * AQPAD + 1];
                a00 = fma2(a0, b.x, a00); a01 = fma2(a0, b.y, a01);
                a10 = fma2(a1, b.x, a10); a11 = fma2(a1, b.y, a11);
            }
        }

        // write qp[q][d]: q = 2ty(+1), d = warp*16 + tx*4
        float4 v0 = { lo2(a00), hi2(a00), lo2(a01), hi2(a01) };
        float4 v1 = { lo2(a10), hi2(a10), lo2(a11), hi2(a11) };
        *(float4*)&qp[(ty * 2 + 0) * DIM + warp * 16 + tx * 4] = v0;
        *(float4*)&qp[(ty * 2 + 1) * DIM + warp * 16 + tx * 4] = v1;
    }
    __syncthreads();

    // ---- phase 2: score (R11 verbatim) ----
    const int doff = warp * 16;

    u64 wx[4], wy[4];
    #pragma unroll
    for (int j = 0; j < 4; j++) {
        ulonglong2 wv = *(const ulonglong2*)(W2 + doff + j * 4);
        wx[j] = wv.x; wy[j] = wv.y;
    }

    for (int c = 0; c < 10; c++) {
        asm volatile("cp.async.wait_group 0;");
        __syncthreads();
        float* cur = sp + (c & 1) * CHUNKF;
        if (c + 1 < 10) prefetch_chunk(sp + ((c + 1) & 1) * CHUNKF, c + 1, tid);

        const ulonglong2* srow = (const ulonglong2*)(cur + lane * SPAD + doff);
        float* pw = pbuf + (warp * QB) * 32;

        #pragma unroll
        for (int h = 0; h < 2; h++) {
            u64 ax[8], ay[8];
            #pragma unroll
            for (int qq = 0; qq < 8; qq++) { ax[qq] = 0ull; ay[qq] = 0ull; }
            u64 t0 = 0ull;

            #pragma unroll
            for (int j = 0; j < 4; j++) {
                ulonglong2 sv = srow[j];
                if (h == 0) {
                    t0 = fma2(sv.x, wx[j], t0);
                    t0 = fma2(sv.y, wy[j], t0);
                }
                #pragma unroll
                for (int qq = 0; qq < 8; qq++) {
                    const int q = h * 8 + qq;
                    ulonglong2 qv = *(const ulonglong2*)(qp + q * DIM + doff + j * 4);
                    u64 t;
                    t = add2(qv.x, sv.x) & ABSMASK; ax[qq] = fma2(t, wx[j], ax[qq]);
                    t = add2(qv.y, sv.y) & ABSMASK; ay[qq] = fma2(t, wy[j], ay[qq]);
                }
            }

            #pragma unroll
            for (int qq = 0; qq < 8; qq++)
                pw[(h * 8 + qq) * 32 + lane] =
                    (lo2(ax[qq]) + hi2(ax[qq])) + (lo2(ay[qq]) + hi2(ay[qq]));
            if (h == 0)
                tbuf[warp * 32 + lane] = lo2(t0) + hi2(t0);
        }

        __syncthreads();

        {
            const int q = warp, sl = lane;
            float s = 0.f;
            #pragma unroll
            for (int w = 0; w < 16; w++)
                s += pbuf[(w * QB + q) * 32 + sl];
            part[q * NS + c * 32 + sl] = s;
        }
        if (warp == 0) {
            float s = 0.f;
            #pragma unroll
            for (int w = 0; w < 16; w++)
                s += tbuf[w * 32 + lane];
            tpart[c * 32 + lane] = s;
        }
    }
    __syncthreads();

    // ---- softmax: warp w owns q = w ----
    {
        const int q = warp;
        float v[10];
        #pragma unroll
        for (int c = 0; c < 10; c++)
            v[c] = 0.5f * (tpart[c * 32 + lane] + part[q * NS + c * 32 + lane]);

        float m = v[0];
        #pragma unroll
        for (int c = 1; c < 10; c++) m = fmaxf(m, v[c]);
        #pragma unroll
        for (int o = 16; o > 0; o >>= 1)
            m = fmaxf(m, __shfl_xor_sync(0xffffffffu, m, o));

        float l = 0.f;
        #pragma unroll
        for (int c = 0; c < 10; c++) {
            float ev = __expf(v[c] - m);
            l += ev;
            atomicAdd(&sacc[q * NWAY + lbl[c * 32 + lane]], ev);
        }
        #pragma unroll
        for (int o = 16; o > 0; o >>= 1)
            l += __shfl_xor_sync(0xffffffffu, l, o);
        const float inv = 1.f / l;
        __syncwarp();

        if (lane < NWAY)
            out[(qbase + q) * NWAY + lane] = sacc[q * NWAY + lane] * inv;
    }
}

// ---------------------------------------------------------------------------
extern "C" void kernel_launch(void* const* d_in, const int* in_sizes, int n_in,
                              void* d_out, int out_size)
{
    (void)in_sizes; (void)n_in; (void)out_size;
    const float* support = (const float*)d_in[0];
    const float* query   = (const float*)d_in[1];
    const int*   labels  = (const int*)d_in[2];
    const float* W1      = (const float*)d_in[3];
    const float* b1      = (const float*)d_in[4];
    const float* W2      = (const float*)d_in[5];
    float* out = (float*)d_out;

    const int s_smem = (2 * SASTG) * 8 + (2 * SBSTG) * 4;  // 52224 B
    cudaFuncSetAttribute(sproj_kernel,
                         cudaFuncAttributeMaxDynamicSharedMemorySize, s_smem);
    sproj_kernel<<<dim3(4, 20), 256, s_smem>>>(support, W1, b1);

    const int f_smem = DIM * AQPAD * 8 +
        (2 * B2STG + 2 * CHUNKF + QB * DIM + 16 * QB * 32 + 16 * 32
         + QB * NS + NS + QB * NWAY) * 4 + NS * 4;         // ~210 KB
    cudaFuncSetAttribute(fused_kernel,
                         cudaFuncAttributeMaxDynamicSharedMemorySize, f_smem);
    fused_kernel<<<NQ / QB, TPB, f_smem>>>(query, W1, labels, W2, out);
}

// round 16
// speedup vs baseline: 1.1918x; 1.1918x over previous
#include <cuda_runtime.h>

#define NQ   2048
#define NS   320
#define DIM  256
#define NWAY 20

typedef unsigned long long u64;

__device__ float g_qproj[NQ * DIM];
__device__ float g_sproj[NS * DIM];

// ---- packed f32x2 helpers ----
__device__ __forceinline__ u64 add2(u64 a, u64 b) {
    u64 d; asm("add.rn.f32x2 %0, %1, %2;" : "=l"(d) : "l"(a), "l"(b)); return d;
}
__device__ __forceinline__ u64 fma2(u64 a, u64 b, u64 c) {
    u64 d; asm("fma.rn.f32x2 %0, %1, %2, %3;" : "=l"(d) : "l"(a), "l"(b), "l"(c)); return d;
}
__device__ __forceinline__ u64 dup2(float x) {
    u64 r; unsigned xi = __float_as_uint(x);
    asm("mov.b64 %0, {%1, %1};" : "=l"(r) : "r"(xi)); return r;
}
__device__ __forceinline__ float lo2(u64 v) { return __uint_as_float((unsigned)v); }
__device__ __forceinline__ float hi2(u64 v) { return __uint_as_float((unsigned)(v >> 32)); }

__device__ __forceinline__ void cpa16(void* dst, const void* src) {
    unsigned sa = (unsigned)__cvta_generic_to_shared(dst);
    asm volatile("cp.async.cg.shared.global [%0], [%1], 16;" :: "r"(sa), "l"(src));
}

// ---------------------------------------------------------------------------
// Kernel A: projections — R6 version verbatim (measured 16.1us)
// ---------------------------------------------------------------------------
#define PBK   64
#define PADA  65
#define PADB  68
#define ASTG  (PBK * PADA)
#define BSTG  (PBK * PADB)

__global__ void __launch_bounds__(256) proj_kernel(
    const float* __restrict__ support, const float* __restrict__ query,
    const float* __restrict__ W1, const float* __restrict__ b1)
{
    extern __shared__ __align__(16) unsigned char psm[];
    u64*   AsD = (u64*)psm;
    float* Bs  = (float*)(AsD + 2 * ASTG);

    const int tile_n = blockIdx.x;
    const int tile_m = blockIdx.y;
    const bool is_sup = (tile_m >= NQ / 64);

    const float* Amat;
    const float* Bmat;
    int m0;
    if (is_sup) { m0 = (tile_m - NQ / 64) * 64; Amat = support; Bmat = W1 + DIM * DIM; }
    else        { m0 = tile_m * 64;             Amat = query;   Bmat = W1; }
    const int n0 = tile_n * 64;

    const int tid = threadIdx.x;
    const int tx = tid & 15;
    const int ty = tid >> 4;

    const int t_m = tid >> 2;
    const int t_k = (tid & 3) * 4;

    const int b_row = tid >> 2;
    const int b_q   = tid & 3;

    const float* Arow = Amat + (m0 + t_m) * DIM;
    const float* Brow = Bmat + b_row * DIM + n0;

    u64 acc[4][2];
    #pragma unroll
    for (int i = 0; i < 4; i++) { acc[i][0] = 0ull; acc[i][1] = 0ull; }

    float4 areg[4];

    #pragma unroll
    for (int u = 0; u < 4; u++)
        areg[u] = *(const float4*)(Arow + t_k + u * 16);
    #pragma unroll
    for (int u = 0; u < 4; u++) {
        const int kk = t_k + u * 16;
        AsD[(kk + 0) * PADA + t_m] = dup2(areg[u].x);
        AsD[(kk + 1) * PADA + t_m] = dup2(areg[u].y);
        AsD[(kk + 2) * PADA + t_m] = dup2(areg[u].z);
        AsD[(kk + 3) * PADA + t_m] = dup2(areg[u].w);
    }
    #pragma unroll
    for (int u = 0; u < 4; u++) {
        const int c4 = b_q + u * 4;
        cpa16(&Bs[b_row * PADB + c4 * 4], Brow + c4 * 4);
    }
    asm volatile("cp.async.commit_group;");

    #pragma unroll
    for (int s = 0; s < 4; s++) {
        const int buf = s & 1;
        asm volatile("cp.async.wait_group 0;");
        __syncthreads();

        if (s < 3) {
            const int k0n = (s + 1) * PBK;
            #pragma unroll
            for (int u = 0; u < 4; u++)
                areg[u] = *(const float4*)(Arow + k0n + t_k + u * 16);
            #pragma unroll
            for (int u = 0; u < 4; u++) {
                const int c4 = b_q + u * 4;
                cpa16(&Bs[(buf ^ 1) * BSTG + b_row * PADB + c4 * 4],
                      Brow + k0n * DIM + c4 * 4);
            }
            asm volatile("cp.async.commit_group;");
        }

        const u64*   aB = AsD + buf * ASTG + ty * 4;
        const float* bB = Bs + buf * BSTG + tx * 4;

        #pragma unroll 8
        for (int k = 0; k < PBK; k++) {
            ulonglong2 b = *(const ulonglong2*)(bB + k * PADB);
            u64 a0 = aB[k * PADA + 0];
            u64 a1 = aB[k * PADA + 1];
            u64 a2 = aB[k * PADA + 2];
            u64 a3 = aB[k * PADA + 3];
            acc[0][0] = fma2(a0, b.x, acc[0][0]); acc[0][1] = fma2(a0, b.y, acc[0][1]);
            acc[1][0] = fma2(a1, b.x, acc[1][0]); acc[1][1] = fma2(a1, b.y, acc[1][1]);
            acc[2][0] = fma2(a2, b.x, acc[2][0]); acc[2][1] = fma2(a2, b.y, acc[2][1]);
            acc[3][0] = fma2(a3, b.x, acc[3][0]); acc[3][1] = fma2(a3, b.y, acc[3][1]);
        }

        if (s < 3) {
            u64* dst = AsD + (buf ^ 1) * ASTG;
            #pragma unroll
            for (int u = 0; u < 4; u++) {
                const int kk = t_k + u * 16;
                dst[(kk + 0) * PADA + t_m] = dup2(areg[u].x);
                dst[(kk + 1) * PADA + t_m] = dup2(areg[u].y);
                dst[(kk + 2) * PADA + t_m] = dup2(areg[u].z);
                dst[(kk + 3) * PADA + t_m] = dup2(areg[u].w);
            }
        }
    }

    #pragma unroll
    for (int i = 0; i < 4; i++) {
        const int m = m0 + ty * 4 + i;
        float v[4] = { lo2(acc[i][0]), hi2(acc[i][0]), lo2(acc[i][1]), hi2(acc[i][1]) };
        #pragma unroll
        for (int j = 0; j < 4; j++) {
            const int n = n0 + tx * 4 + j;
            if (is_sup) g_sproj[m * DIM + n] = v[j] + __ldg(b1 + n);
            else        g_qproj[m * DIM + n] = v[j];
        }
    }
}

// ---------------------------------------------------------------------------
// Kernel B: QB=8, 256 threads = 8 warps, warp = 32-dim d-team, 2 BLOCKS/SM.
// Two independent barrier domains per SM interleave their bubbles.
// Ts fused; atomic-free reduce.
//   score'[q,s] = 0.5*(Ts[s] + sum_d |qp+sp| * W2[d])
// ---------------------------------------------------------------------------
#define QB 8
#define TPB 256
#define NW 8
#define SPAD 260
#define CHUNKF 8320
#define ABSMASK 0x7FFFFFFF7FFFFFFFull

__device__ __forceinline__ void prefetch_chunk(float* buf, int c, int tid) {
    #pragma unroll
    for (int i = 0; i < 8; i++) {
        int f   = tid + i * TPB;     // float4 idx 0..2047
        int row = f >> 6;
        int c4  = f & 63;
        cpa16(buf + row * SPAD + c4 * 4, g_sproj + (c * 32 + row) * DIM + c4 * 4);
    }
    asm volatile("cp.async.commit_group;");
}

__global__ void __launch_bounds__(TPB, 2) score_kernel(
    const int* __restrict__ labels, const float* __restrict__ W2,
    float* __restrict__ out)
{
    extern __shared__ float sm[];
    float* sp    = sm;                        // 2 * 8320 = 16640
    float* qp    = sm + 2 * CHUNKF;           // 8*256 = 2048
    float* w2s   = qp + QB * DIM;             // 256
    float* pbuf  = w2s + DIM;                 // 8 warps * 8 q * 32 = 2048
    float* tbuf  = pbuf + NW * QB * 32;       // 8*32 = 256
    float* part  = tbuf + NW * 32;            // 8*320 = 2560
    float* tpart = part + QB * NS;            // 320
    float* sacc  = tpart + NS;                // 8*20 = 160
    int*   lbl   = (int*)(sacc + QB * NWAY);  // 320

    const int tid  = threadIdx.x;
    const int warp = tid >> 5;                // d-team: 32 dims
    const int lane = tid & 31;                // s within chunk
    const int qbase = blockIdx.x * QB;

    prefetch_chunk(sp, 0, tid);

    {
        const float4* qsrc = (const float4*)(g_qproj + qbase * DIM);
        float4* qpv = (float4*)qp;
        #pragma unroll
        for (int i = 0; i < 2; i++) qpv[tid + i * TPB] = qsrc[tid + i * TPB];
        if (tid < DIM / 4) ((float4*)w2s)[tid] = ((const float4*)W2)[tid];
        for (int i = tid; i < NS; i += TPB) lbl[i] = labels[i];   // <-- fix
        if (tid < QB * NWAY) sacc[tid] = 0.f;
    }

    const int doff = warp * 32;               // this team's 32-dim slice

    for (int c = 0; c < 10; c++) {
        asm volatile("cp.async.wait_group 0;");
        __syncthreads();                       // chunk ready; pbuf free
        float* cur = sp + (c & 1) * CHUNKF;
        if (c + 1 < 10) prefetch_chunk(sp + ((c + 1) & 1) * CHUNKF, c + 1, tid);

        const ulonglong2* srow = (const ulonglong2*)(cur + lane * SPAD + doff);
        const ulonglong2* w2p  = (const ulonglong2*)(w2s + doff);
        float* pw = pbuf + (warp * QB) * 32;

        u64 ax[QB], ay[QB];
        #pragma unroll
        for (int q = 0; q < QB; q++) { ax[q] = 0ull; ay[q] = 0ull; }
        u64 t0 = 0ull;

        #pragma unroll
        for (int j = 0; j < 8; j++) {          // 32 dims = 8 ulonglong2
            ulonglong2 sv = srow[j];
            ulonglong2 wv = w2p[j];
            t0 = fma2(sv.x, wv.x, t0);
            t0 = fma2(sv.y, wv.y, t0);
            #pragma unroll
            for (int q = 0; q < QB; q++) {
                ulonglong2 qv = *(const ulonglong2*)(qp + q * DIM + doff + j * 4);
                u64 t;
                t = add2(qv.x, sv.x) & ABSMASK; ax[q] = fma2(t, wv.x, ax[q]);
                t = add2(qv.y, sv.y) & ABSMASK; ay[q] = fma2(t, wv.y, ay[q]);
            }
        }

        #pragma unroll
        for (int q = 0; q < QB; q++)
            pw[q * 32 + lane] =
                (lo2(ax[q]) + hi2(ax[q])) + (lo2(ay[q]) + hi2(ay[q]));
        tbuf[warp * 32 + lane] = lo2(t0) + hi2(t0);

        __syncthreads();

        // reduce: warp w (=q) sums 8 team partials; warp 0 also reduces Ts
        {
            const int q = warp, sl = lane;
            float s = 0.f;
            #pragma unroll
            for (int w = 0; w < NW; w++)
                s += pbuf[(w * QB + q) * 32 + sl];
            part[q * NS + c * 32 + sl] = s;
        }
        if (warp == 0) {
            float s = 0.f;
            #pragma unroll
            for (int w = 0; w < NW; w++)
                s += tbuf[w * 32 + lane];
            tpart[c * 32 + lane] = s;
        }
        // next top-of-loop __syncthreads separates reduce from next writes
    }
    __syncthreads();

    // ---- softmax: warp w owns q = w (8 warps, 8 q) ----
    {
        const int q = warp;
        float v[10];
        #pragma unroll
        for (int c = 0; c < 10; c++)
            v[c] = 0.5f * (tpart[c * 32 + lane] + part[q * NS + c * 32 + lane]);

        float m = v[0];
        #pragma unroll
        for (int c = 1; c < 10; c++) m = fmaxf(m, v[c]);
        #pragma unroll
        for (int o = 16; o > 0; o >>= 1)
            m = fmaxf(m, __shfl_xor_sync(0xffffffffu, m, o));

        float l = 0.f;
        #pragma unroll
        for (int c = 0; c < 10; c++) {
            float ev = __expf(v[c] - m);
            l += ev;
            atomicAdd(&sacc[q * NWAY + lbl[c * 32 + lane]], ev);
        }
        #pragma unroll
        for (int o = 16; o > 0; o >>= 1)
            l += __shfl_xor_sync(0xffffffffu, l, o);
        const float inv = 1.f / l;
        __syncwarp();

        if (lane < NWAY)
            out[(qbase + q) * NWAY + lane] = sacc[q * NWAY + lane] * inv;
    }
}

// ---------------------------------------------------------------------------
extern "C" void kernel_launch(void* const* d_in, const int* in_sizes, int n_in,
                              void* d_out, int out_size)
{
    (void)in_sizes; (void)n_in; (void)out_size;
    const float* support = (const float*)d_in[0];
    const float* query   = (const float*)d_in[1];
    const int*   labels  = (const int*)d_in[2];
    const float* W1      = (const float*)d_in[3];
    const float* b1      = (const float*)d_in[4];
    const float* W2      = (const float*)d_in[5];
    float* out = (float*)d_out;

    const int proj_smem = (2 * ASTG) * 8 + (2 * BSTG) * 4;  // 101376 B
    cudaFuncSetAttribute(proj_kernel,
                         cudaFuncAttributeMaxDynamicSharedMemorySize, proj_smem);
    proj_kernel<<<dim3(4, 37), 256, proj_smem>>>(support, query, W1, b1);

    const int smem_bytes =
        (2 * CHUNKF + QB * DIM + DIM + NW * QB * 32 + NW * 32
         + QB * NS + NS + QB * NWAY) * 4 + NS * 4;   // ~98 KB
    cudaFuncSetAttribute(score_kernel,
                         cudaFuncAttributeMaxDynamicSharedMemorySize, smem_bytes);
    score_kernel<<<NQ / QB, TPB, smem_bytes>>>(labels, W2, out);
}

// round 17
// speedup vs baseline: 1.2583x; 1.0558x over previous
#include <cuda_runtime.h>

#define NQ   2048
#define NS   320
#define DIM  256
#define NWAY 20

typedef unsigned long long u64;

__device__ float g_qproj[NQ * DIM];
__device__ float g_sproj[NS * DIM];

__device__ __forceinline__ u64 add2(u64 a, u64 b) {
    u64 d; asm("add.rn.f32x2 %0, %1, %2;" : "=l"(d) : "l"(a), "l"(b)); return d;
}
__device__ __forceinline__ u64 fma2(u64 a, u64 b, u64 c) {
    u64 d; asm("fma.rn.f32x2 %0, %1, %2, %3;" : "=l"(d) : "l"(a), "l"(b), "l"(c)); return d;
}
__device__ __forceinline__ u64 dup2(float x) {
    u64 r; unsigned xi = __float_as_uint(x);
    asm("mov.b64 %0, {%1, %1};" : "=l"(r) : "r"(xi)); return r;
}
__device__ __forceinline__ float lo2(u64 v) { return __uint_as_float((unsigned)v); }
__device__ __forceinline__ float hi2(u64 v) { return __uint_as_float((unsigned)(v >> 32)); }

__device__ __forceinline__ void cpa16(void* dst, const void* src) {
    unsigned sa = (unsigned)__cvta_generic_to_shared(dst);
    asm volatile("cp.async.cg.shared.global [%0], [%1], 16;" :: "r"(sa), "l"(src));
}

// ---------------------------------------------------------------------------
// Kernel A: projections — R6 + A reads via LDS.128 (PADA=66 for alignment)
// ---------------------------------------------------------------------------
#define PBK   64
#define PADA  66            // u64 stride per k-row (even -> 16B aligned pairs)
#define PADB  68
#define ASTG  (PBK * PADA)  // 4224 u64
#define BSTG  (PBK * PADB)

__global__ void __launch_bounds__(256) proj_kernel(
    const float* __restrict__ support, const float* __restrict__ query,
    const float* __restrict__ W1, const float* __restrict__ b1)
{
    extern __shared__ __align__(16) unsigned char psm[];
    u64*   AsD = (u64*)psm;
    float* Bs  = (float*)(AsD + 2 * ASTG);

    const int tile_n = blockIdx.x;
    const int tile_m = blockIdx.y;
    const bool is_sup = (tile_m >= NQ / 64);

    const float* Amat;
    const float* Bmat;
    int m0;
    if (is_sup) { m0 = (tile_m - NQ / 64) * 64; Amat = support; Bmat = W1 + DIM * DIM; }
    else        { m0 = tile_m * 64;             Amat = query;   Bmat = W1; }
    const int n0 = tile_n * 64;

    const int tid = threadIdx.x;
    const int tx = tid & 15;
    const int ty = tid >> 4;

    const int t_m = tid >> 2;
    const int t_k = (tid & 3) * 4;

    const int b_row = tid >> 2;
    const int b_q   = tid & 3;

    const float* Arow = Amat + (m0 + t_m) * DIM;
    const float* Brow = Bmat + b_row * DIM + n0;

    u64 acc[4][2];
    #pragma unroll
    for (int i = 0; i < 4; i++) { acc[i][0] = 0ull; acc[i][1] = 0ull; }

    float4 areg[4];

    #pragma unroll
    for (int u = 0; u < 4; u++)
        areg[u] = *(const float4*)(Arow + t_k + u * 16);
    #pragma unroll
    for (int u = 0; u < 4; u++) {
        const int kk = t_k + u * 16;
        AsD[(kk + 0) * PADA + t_m] = dup2(areg[u].x);
        AsD[(kk + 1) * PADA + t_m] = dup2(areg[u].y);
        AsD[(kk + 2) * PADA + t_m] = dup2(areg[u].z);
        AsD[(kk + 3) * PADA + t_m] = dup2(areg[u].w);
    }
    #pragma unroll
    for (int u = 0; u < 4; u++) {
        const int c4 = b_q + u * 4;
        cpa16(&Bs[b_row * PADB + c4 * 4], Brow + c4 * 4);
    }
    asm volatile("cp.async.commit_group;");

    #pragma unroll
    for (int s = 0; s < 4; s++) {
        const int buf = s & 1;
        asm volatile("cp.async.wait_group 0;");
        __syncthreads();

        if (s < 3) {
            const int k0n = (s + 1) * PBK;
            #pragma unroll
            for (int u = 0; u < 4; u++)
                areg[u] = *(const float4*)(Arow + k0n + t_k + u * 16);
            #pragma unroll
            for (int u = 0; u < 4; u++) {
                const int c4 = b_q + u * 4;
                cpa16(&Bs[(buf ^ 1) * BSTG + b_row * PADB + c4 * 4],
                      Brow + k0n * DIM + c4 * 4);
            }
            asm volatile("cp.async.commit_group;");
        }

        const u64*   aB = AsD + buf * ASTG + ty * 4;
        const float* bB = Bs + buf * BSTG + tx * 4;

        #pragma unroll 8
        for (int k = 0; k < PBK; k++) {
            ulonglong2 b   = *(const ulonglong2*)(bB + k * PADB);
            ulonglong2 a01 = *(const ulonglong2*)(aB + k * PADA);
            ulonglong2 a23 = *(const ulonglong2*)(aB + k * PADA + 2);
            acc[0][0] = fma2(a01.x, b.x, acc[0][0]); acc[0][1] = fma2(a01.x, b.y, acc[0][1]);
            acc[1][0] = fma2(a01.y, b.x, acc[1][0]); acc[1][1] = fma2(a01.y, b.y, acc[1][1]);
            acc[2][0] = fma2(a23.x, b.x, acc[2][0]); acc[2][1] = fma2(a23.x, b.y, acc[2][1]);
            acc[3][0] = fma2(a23.y, b.x, acc[3][0]); acc[3][1] = fma2(a23.y, b.y, acc[3][1]);
        }

        if (s < 3) {
            u64* dst = AsD + (buf ^ 1) * ASTG;
            #pragma unroll
            for (int u = 0; u < 4; u++) {
                const int kk = t_k + u * 16;
                dst[(kk + 0) * PADA + t_m] = dup2(areg[u].x);
                dst[(kk + 1) * PADA + t_m] = dup2(areg[u].y);
                dst[(kk + 2) * PADA + t_m] = dup2(areg[u].z);
                dst[(kk + 3) * PADA + t_m] = dup2(areg[u].w);
            }
        }
    }

    #pragma unroll
    for (int i = 0; i < 4; i++) {
        const int m = m0 + ty * 4 + i;
        float v[4] = { lo2(acc[i][0]), hi2(acc[i][0]), lo2(acc[i][1]), hi2(acc[i][1]) };
        #pragma unroll
        for (int j = 0; j < 4; j++) {
            const int n = n0 + tx * 4 + j;
            if (is_sup) g_sproj[m * DIM + n] = v[j] + __ldg(b1 + n);
            else        g_qproj[m * DIM + n] = v[j];
        }
    }
}

// ---------------------------------------------------------------------------
// Kernel B: QB=14, grid 147 (fills the chip). warp = 16-dim d-team,
// 14 q in two passes of 7, srow hoisted, Ts fused, atomic-free reduce.
//   score'[q,s] = 0.5*(Ts[s] + sum_d |qp+sp| * W2[d])
// ---------------------------------------------------------------------------
#define QB 14
#define TPB 512
#define SPAD 260
#define CHUNKF 8320
#define ABSMASK 0x7FFFFFFF7FFFFFFFull

__device__ __forceinline__ void prefetch_chunk(float* buf, int c, int tid) {
    #pragma unroll
    for (int i = 0; i < 4; i++) {
        int f   = tid + i * TPB;
        int row = f >> 6;
        int c4  = f & 63;
        cpa16(buf + row * SPAD + c4 * 4, g_sproj + (c * 32 + row) * DIM + c4 * 4);
    }
    asm volatile("cp.async.commit_group;");
}

__global__ void __launch_bounds__(TPB, 1) score_kernel(
    const int* __restrict__ labels, const float* __restrict__ W2,
    float* __restrict__ out)
{
    extern __shared__ float sm[];
    float* sp    = sm;                        // 2*8320
    float* qp    = sm + 2 * CHUNKF;           // 14*256 = 3584
    float* pbuf  = qp + QB * DIM;             // 16*14*32 = 7168
    float* tbuf  = pbuf + 16 * QB * 32;       // 512
    float* part  = tbuf + 16 * 32;            // 14*320 = 4480
    float* tpart = part + QB * NS;            // 320
    float* sacc  = tpart + NS;                // 14*20 = 280
    int*   lbl   = (int*)(sacc + QB * NWAY);  // 320

    const int tid  = threadIdx.x;
    const int warp = tid >> 5;
    const int lane = tid & 31;
    const int qbase = blockIdx.x * QB;

    prefetch_chunk(sp, 0, tid);

    {
        // qp rows clamped to valid range (tail block reads row 2047; unused)
        for (int f = tid; f < QB * 64; f += TPB) {
            int row = f >> 6;
            int c4  = f & 63;
            int grow = qbase + row; if (grow > NQ - 1) grow = NQ - 1;
            ((float4*)qp)[row * 64 + c4] =
                ((const float4*)(g_qproj + grow * DIM))[c4];
        }
        for (int i = tid; i < NS; i += TPB) lbl[i] = labels[i];
        if (tid < QB * NWAY) sacc[tid] = 0.f;
    }

    const int doff = warp * 16;

    u64 wx[4], wy[4];
    #pragma unroll
    for (int j = 0; j < 4; j++) {
        ulonglong2 wv = *(const ulonglong2*)(W2 + doff + j * 4);
        wx[j] = wv.x; wy[j] = wv.y;
    }

    for (int c = 0; c < 10; c++) {
        asm volatile("cp.async.wait_group 0;");
        __syncthreads();
        float* cur = sp + (c & 1) * CHUNKF;
        if (c + 1 < 10) prefetch_chunk(sp + ((c + 1) & 1) * CHUNKF, c + 1, tid);

        const ulonglong2* srp = (const ulonglong2*)(cur + lane * SPAD + doff);
        ulonglong2 sv[4];
        #pragma unroll
        for (int j = 0; j < 4; j++) sv[j] = srp[j];   // hoisted once per chunk

        float* pw = pbuf + (warp * QB) * 32;

        #pragma unroll
        for (int h = 0; h < 2; h++) {                 // q-halves of 7
            u64 ax[7], ay[7];
            #pragma unroll
            for (int qq = 0; qq < 7; qq++) { ax[qq] = 0ull; ay[qq] = 0ull; }
            u64 t0 = 0ull;

            #pragma unroll
            for (int j = 0; j < 4; j++) {
                if (h == 0) {
                    t0 = fma2(sv[j].x, wx[j], t0);
                    t0 = fma2(sv[j].y, wy[j], t0);
                }
                #pragma unroll
                for (int qq = 0; qq < 7; qq++) {
                    const int q = h * 7 + qq;
                    ulonglong2 qv = *(const ulonglong2*)(qp + q * DIM + doff + j * 4);
                    u64 t;
                    t = add2(qv.x, sv[j].x) & ABSMASK; ax[qq] = fma2(t, wx[j], ax[qq]);
                    t = add2(qv.y, sv[j].y) & ABSMASK; ay[qq] = fma2(t, wy[j], ay[qq]);
                }
            }

            #pragma unroll
            for (int qq = 0; qq < 7; qq++)
                pw[(h * 7 + qq) * 32 + lane] =
                    (lo2(ax[qq]) + hi2(ax[qq])) + (lo2(ay[qq]) + hi2(ay[qq]));
            if (h == 0)
                tbuf[warp * 32 + lane] = lo2(t0) + hi2(t0);
        }

        __syncthreads();

        // reduce: warps 0..13 -> part (q = warp); warp 14 -> tpart
        if (warp < QB) {
            const int q = warp, sl = lane;
            float s = 0.f;
            #pragma unroll
            for (int w = 0; w < 16; w++)
                s += pbuf[(w * QB + q) * 32 + sl];
            part[q * NS + c * 32 + sl] = s;
        } else if (warp == 14) {
            float s = 0.f;
            #pragma unroll
            for (int w = 0; w < 16; w++)
                s += tbuf[w * 32 + lane];
            tpart[c * 32 + lane] = s;
        }
    }
    __syncthreads();

    // ---- softmax: warp w (<14) owns q = w ----
    if (warp < QB && qbase + warp < NQ) {
        const int q = warp;
        float v[10];
        #pragma unroll
        for (int c = 0; c < 10; c++)
            v[c] = 0.5f * (tpart[c * 32 + lane] + part[q * NS + c * 32 + lane]);

        float m = v[0];
        #pragma unroll
        for (int c = 1; c < 10; c++) m = fmaxf(m, v[c]);
        #pragma unroll
        for (int o = 16; o > 0; o >>= 1)
            m = fmaxf(m, __shfl_xor_sync(0xffffffffu, m, o));

        float l = 0.f;
        #pragma unroll
        for (int c = 0; c < 10; c++) {
            float ev = __expf(v[c] - m);
            l += ev;
            atomicAdd(&sacc[q * NWAY + lbl[c * 32 + lane]], ev);
        }
        #pragma unroll
        for (int o = 16; o > 0; o >>= 1)
            l += __shfl_xor_sync(0xffffffffu, l, o);
        const float inv = 1.f / l;
        __syncwarp();

        if (lane < NWAY)
            out[(qbase + q) * NWAY + lane] = sacc[q * NWAY + lane] * inv;
    }
}

// ---------------------------------------------------------------------------
extern "C" void kernel_launch(void* const* d_in, const int* in_sizes, int n_in,
                              void* d_out, int out_size)
{
    (void)in_sizes; (void)n_in; (void)out_size;
    const float* support = (const float*)d_in[0];
    const float* query   = (const float*)d_in[1];
    const int*   labels  = (const int*)d_in[2];
    const float* W1      = (const float*)d_in[3];
    const float* b1      = (const float*)d_in[4];
    const float* W2      = (const float*)d_in[5];
    float* out = (float*)d_out;

    const int proj_smem = (2 * ASTG) * 8 + (2 * BSTG) * 4;  // 102400 B
    cudaFuncSetAttribute(proj_kernel,
                         cudaFuncAttributeMaxDynamicSharedMemorySize, proj_smem);
    proj_kernel<<<dim3(4, 37), 256, proj_smem>>>(support, query, W1, b1);

    const int nblocks = (NQ + QB - 1) / QB;   // 147
    const int smem_bytes =
        (2 * CHUNKF + QB * DIM + 16 * QB * 32 + 16 * 32 + QB * NS + NS
         + QB * NWAY) * 4 + NS * 4;
    cudaFuncSetAttribute(score_kernel,
                         cudaFuncAttributeMaxDynamicSharedMemorySize, smem_bytes);
    score_kernel<<<nblocks, TPB, smem_bytes>>>(labels, W2, out);
}